// round 6
// baseline (speedup 1.0000x reference)
#include <cuda_runtime.h>

#define T_STEPS 131072
#define FEATS   8
#define HIDDEN  256
#define BUF     50
#define MAX_K   10
#define BLK     256
#define TROWS   128                      // rows per tile
#define BROWS   256                      // rows per block (2 tiles)
#define SP_N2   (BROWS + BUF - 1)        // 305 staged prices
#define DOFF2(k) (((k) - 1) * SP_N2 - (((k) - 1) * (k)) / 2)
#define D_TOTAL2 (MAX_K * SP_N2 - (MAX_K * (MAX_K + 1)) / 2)   // 2995

__device__ __forceinline__ float kconst_log(int k) {
    constexpr float LOGK[11] = {0.f, 0.f, 0.69314718f, 1.09861229f, 1.38629436f,
                                1.60943791f, 1.79175947f, 1.94591015f,
                                2.07944154f, 2.19722458f, 2.30258509f};
    return LOGK[k];
}

// Lk for one k: weighted sum of lag-k diffs, weights folded at compile time.
template<int K>
__device__ __forceinline__ float lk_acc(const float* __restrict__ dk) {
    float acc = 0.0f;
    #pragma unroll
    for (int q = 0; q + K <= BUF - 1; q++) {
        const int   m   = q % K;
        const int   len = (BUF - 1 - m) / K + 1;
        const float wgt = 49.0f / ((float)len * (float)(K * K));
        acc = fmaf(wgt, dk[q], acc);
    }
    return acc;
}

// Branchless log-log fit accumulation (safe for acc == 0).
__device__ __forceinline__ void fit_add(float acc, float xk,
        float& c, float& sx, float& sy, float& sxy, float& sxx) {
    const bool  g   = acc > 0.0f;
    const float p   = g ? 1.0f : 0.0f;
    const float yk  = __logf(fmaxf(acc, 1e-37f));
    const float ykm = g ? yk : 0.0f;
    c += p; sx += p * xk; sy += ykm; sxy += ykm * xk; sxx += p * (xk * xk);
}

// Plain (non-jammed) partials over this half's 5 k values.
template<int HALF>
__device__ __forceinline__ void steady5(const float* __restrict__ s_d, int idx,
        float& c, float& sx, float& sy, float& sxy, float& sxx)
{
    {
        float a = lk_acc<1 + HALF>(s_d + DOFF2(1 + HALF) + idx);
        fit_add(a, kconst_log(1 + HALF), c, sx, sy, sxy, sxx);
    }{
        float a = lk_acc<3 + HALF>(s_d + DOFF2(3 + HALF) + idx);
        fit_add(a, kconst_log(3 + HALF), c, sx, sy, sxy, sxx);
    }{
        float a = lk_acc<5 + HALF>(s_d + DOFF2(5 + HALF) + idx);
        fit_add(a, kconst_log(5 + HALF), c, sx, sy, sxy, sxx);
    }{
        float a = lk_acc<7 + HALF>(s_d + DOFF2(7 + HALF) + idx);
        fit_add(a, kconst_log(7 + HALF), c, sx, sy, sxy, sxx);
    }{
        float a = lk_acc<9 + HALF>(s_d + DOFF2(9 + HALF) + idx);
        fit_add(a, kconst_log(9 + HALF), c, sx, sy, sxy, sxx);
    }
}

// Jammed region: store chunk of tile `s_hs` interleaved with one k of compute.
#define STORE_RANGE(S0, S1)                                                   \
    _Pragma("unroll")                                                         \
    for (int rr = (S0); rr < (S1); rr++) {                                    \
        const int   row = (rr << 2) | r0;                                     \
        const float h   = s_hs[row];                                         \
        float4 o;                                                             \
        o.x = fmaxf(fmaf(h, w4.x, b4.x), 0.0f);                               \
        o.y = fmaxf(fmaf(h, w4.y, b4.y), 0.0f);                               \
        o.z = fmaxf(fmaf(h, w4.z, b4.z), 0.0f);                               \
        o.w = fmaxf(fmaf(h, w4.w, b4.w), 0.0f);                               \
        __stcs(ob0 + (size_t)row * (HIDDEN / 4), o);                          \
    }

#define JAM_CHUNK(KV, S0, S1)                                                 \
    {                                                                         \
        float a = lk_acc<KV>(s_d + DOFF2(KV) + idx);                          \
        fit_add(a, kconst_log(KV), c, sx, sy, sxy, sxx);                      \
        STORE_RANGE(S0, S1)                                                   \
    }

__global__ __launch_bounds__(BLK)
void fused_hfd_kernel(const float* __restrict__ x,
                      const float* __restrict__ w,
                      const float* __restrict__ b,
                      float4* __restrict__ out)
{
    __shared__ float s_p[SP_N2];           // prices [t0-49, t0+255]
    __shared__ float s_d[D_TOTAL2];        // lag-diff tables, all k
    __shared__ float s_h0[TROWS], s_h1[TROWS];
    __shared__ float s_part[5][TROWS];     // half-1 partials (reused per tile)

    const int t0     = blockIdx.x * BROWS;
    const int base_g = t0 - (BUF - 1);

    // Hoisted Phase-B constants (hide L2 latency behind compute).
    const int j  = threadIdx.x & 63;
    const int r0 = threadIdx.x >> 6;
    const float4 w4 = __ldg(((const float4*)w) + j);
    const float4 b4 = __ldg(((const float4*)b) + j);
    float4* const ob0 = out + (size_t)t0 * (HIDDEN / 4) + j;           // tile0
    float4* const ob1 = ob0 + (size_t)TROWS * (HIDDEN / 4);            // tile1

    // 1) Stage close-price column (stride 8 floats), coalesced.
    for (int i = threadIdx.x; i < SP_N2; i += BLK) {
        const int g = base_g + i;
        s_p[i] = (g >= 0) ? x[g * FEATS + 3] : 0.0f;
    }
    __syncthreads();

    // 2) Lag-diff tables d_k[i] = |p[i+k]-p[i]| over the whole 305 window.
    #pragma unroll
    for (int k = 1; k <= MAX_K; k++) {
        const int n = SP_N2 - k;
        for (int i = threadIdx.x; i < n; i += BLK)
            s_d[DOFF2(k) + i] = fabsf(s_p[i + k] - s_p[i]);
    }
    __syncthreads();

    const int wid  = threadIdx.x >> 5;
    const int lane = threadIdx.x & 31;
    const int half = wid & 1;                    // warp-uniform k-set parity
    const int ts   = ((wid >> 1) << 5) | lane;   // row 0..127 within a tile

    // 3) Tile-0 compute.
    {
        float c = 0.f, sx = 0.f, sy = 0.f, sxy = 0.f, sxx = 0.f;
        if (half) steady5<1>(s_d, ts, c, sx, sy, sxy, sxx);
        else      steady5<0>(s_d, ts, c, sx, sy, sxy, sxx);
        if (half) {
            s_part[0][ts] = c;   s_part[1][ts] = sx;  s_part[2][ts] = sy;
            s_part[3][ts] = sxy; s_part[4][ts] = sxx;
        }
        __syncthreads();
        if (!half) {
            c   += s_part[0][ts]; sx  += s_part[1][ts]; sy += s_part[2][ts];
            sxy += s_part[3][ts]; sxx += s_part[4][ts];
            float hfd = 0.0f;
            const float denom = c * sxx - sx * sx;
            if (c > 1.0f && denom != 0.0f)
                hfd = -(c * sxy - sx * sy) / denom;

            // Warmup (block 0 only): rows 0..48 use growing windows.
            if (blockIdx.x == 0 && ts <= BUF - 2) {
                hfd = 0.0f;
                if (ts >= MAX_K) {
                    const int   nm1  = ts;
                    const float nm1f = (float)nm1;
                    const int   base = BUF - 1;       // s_p idx of price[0]
                    float c2=0.f, sx2=0.f, sy2=0.f, sxy2=0.f, sxx2=0.f;
                    for (int k = 1; k <= MAX_K; k++) {
                        float acc = 0.0f;
                        for (int m = 0; m < k; m++) {
                            const int len = (nm1 - m) / k + 1;
                            float s = 0.0f;
                            for (int q = m; q + k <= nm1; q += k)
                                s += fabsf(s_p[base + q + k] - s_p[base + q]);
                            if (len >= 2)
                                acc += s * nm1f / ((float)len * (float)k);
                        }
                        const float Lk = acc / (float)k;
                        if (Lk > 0.0f) {
                            const float yk = __logf(Lk);
                            const float xk = __logf((float)k);
                            c2 += 1.f; sx2 += xk; sy2 += yk;
                            sxy2 += yk * xk; sxx2 += xk * xk;
                        }
                    }
                    const float dn = c2 * sxx2 - sx2 * sx2;
                    if (c2 > 1.0f && dn != 0.0f)
                        hfd = -(c2 * sxy2 - sx2 * sy2) / dn;
                }
            }
            s_h0[ts] = hfd;
        }
        __syncthreads();
    }

    // 4) JAM: store tile-0 interleaved with tile-1 compute (one basic block).
    {
        float c = 0.f, sx = 0.f, sy = 0.f, sxy = 0.f, sxx = 0.f;
        const int idx = TROWS + ts;                 // tile-1 row in d tables
        const float* __restrict__ s_hs = s_h0;
        if (half) {
            JAM_CHUNK(2,  0,  6)
            JAM_CHUNK(4,  6, 12)
            JAM_CHUNK(6, 12, 18)
            JAM_CHUNK(8, 18, 24)
            JAM_CHUNK(10,24, 32)
        } else {
            JAM_CHUNK(1,  0,  6)
            JAM_CHUNK(3,  6, 12)
            JAM_CHUNK(5, 12, 18)
            JAM_CHUNK(7, 18, 24)
            JAM_CHUNK(9, 24, 32)
        }
        if (half) {
            s_part[0][ts] = c;   s_part[1][ts] = sx;  s_part[2][ts] = sy;
            s_part[3][ts] = sxy; s_part[4][ts] = sxx;
        }
        __syncthreads();
        if (!half) {
            c   += s_part[0][ts]; sx  += s_part[1][ts]; sy += s_part[2][ts];
            sxy += s_part[3][ts]; sxx += s_part[4][ts];
            float hfd = 0.0f;
            const float denom = c * sxx - sx * sx;
            if (c > 1.0f && denom != 0.0f)
                hfd = -(c * sxy - sx * sy) / denom;
            s_h1[ts] = hfd;
        }
        __syncthreads();
    }

    // 5) Store tile-1.
    #pragma unroll 8
    for (int rr = 0; rr < 32; rr++) {
        const int   row = (rr << 2) | r0;
        const float h   = s_h1[row];
        float4 o;
        o.x = fmaxf(fmaf(h, w4.x, b4.x), 0.0f);
        o.y = fmaxf(fmaf(h, w4.y, b4.y), 0.0f);
        o.z = fmaxf(fmaf(h, w4.z, b4.z), 0.0f);
        o.w = fmaxf(fmaf(h, w4.w, b4.w), 0.0f);
        __stcs(ob1 + (size_t)row * (HIDDEN / 4), o);
    }
}

// ---------------------------------------------------------------------------
extern "C" void kernel_launch(void* const* d_in, const int* in_sizes, int n_in,
                              void* d_out, int out_size)
{
    const float* x = (const float*)d_in[0];   // [T, 8]
    const float* w = (const float*)d_in[1];   // [256, 1] -> flat [256]
    const float* b = (const float*)d_in[2];   // [256]
    float4* out = (float4*)d_out;             // [T, 256] f32

    fused_hfd_kernel<<<T_STEPS / BROWS, BLK>>>(x, w, b, out);
}

// round 7
// speedup vs baseline: 1.1039x; 1.1039x over previous
#include <cuda_runtime.h>

#define T_STEPS 131072
#define FEATS   8
#define HIDDEN  256
#define BUF     50
#define MAX_K   10
#define BLK     128
#define ROWS    128                    // timesteps per block (1 per thread)
#define SP_N    (ROWS + BUF - 1)       // 177 staged prices
#define DOFF(k) (((k) - 1) * SP_N - (((k) - 1) * (k)) / 2)
#define D_TOTAL (MAX_K * SP_N - (MAX_K * (MAX_K + 1)) / 2)   // 1715

__device__ __forceinline__ float kconst_log(int k) {
    constexpr float LOGK[11] = {0.f, 0.f, 0.69314718f, 1.09861229f, 1.38629436f,
                                1.60943791f, 1.79175947f, 1.94591015f,
                                2.07944154f, 2.19722458f, 2.30258509f};
    return LOGK[k];
}

// Lk for one k: weighted sum of lag-k diffs, weights folded at compile time.
template<int K>
__device__ __forceinline__ float lk_acc(const float* __restrict__ dk) {
    float acc = 0.0f;
    #pragma unroll
    for (int q = 0; q + K <= BUF - 1; q++) {
        const int   m   = q % K;
        const int   len = (BUF - 1 - m) / K + 1;
        const float wgt = 49.0f / ((float)len * (float)(K * K));
        acc = fmaf(wgt, dk[q], acc);
    }
    return acc;
}

// Branchless log-log fit accumulation (safe for acc == 0).
__device__ __forceinline__ void fit_add(float acc, float xk,
        float& c, float& sx, float& sy, float& sxy, float& sxx) {
    const bool  g   = acc > 0.0f;
    const float p   = g ? 1.0f : 0.0f;
    const float yk  = __logf(fmaxf(acc, 1e-37f));
    const float ykm = g ? yk : 0.0f;
    c += p; sx += p * xk; sy += ykm; sxy += ykm * xk; sxx += p * (xk * xk);
}

template<int K>
__device__ __forceinline__ void step_k(const float* __restrict__ s_d, int ts,
        float& c, float& sx, float& sy, float& sxy, float& sxx) {
    const float a = lk_acc<K>(s_d + DOFF(K) + ts);
    fit_add(a, kconst_log(K), c, sx, sy, sxy, sxx);
}

__global__ __launch_bounds__(BLK, 12)
void fused_hfd_kernel(const float* __restrict__ x,
                      const float* __restrict__ w,
                      const float* __restrict__ b,
                      float4* __restrict__ out)
{
    __shared__ float s_p[SP_N];            // prices [t0-49, t0+127]
    __shared__ float s_d[D_TOTAL];         // lag-diff tables, all k

    const int t0     = blockIdx.x * ROWS;
    const int base_g = t0 - (BUF - 1);
    const int tid    = threadIdx.x;

    // 1) Stage close-price column (stride 8 floats), coalesced. 2 passes.
    for (int i = tid; i < SP_N; i += BLK) {
        const int g = base_g + i;
        s_p[i] = (g >= 0) ? x[g * FEATS + 3] : 0.0f;
    }
    __syncthreads();

    // 2) Lag-diff tables d_k[i] = |p[i+k]-p[i]| (computed once per block).
    #pragma unroll
    for (int k = 1; k <= MAX_K; k++) {
        const int n = SP_N - k;
        for (int i = tid; i < n; i += BLK)
            s_d[DOFF(k) + i] = fabsf(s_p[i + k] - s_p[i]);
    }
    __syncthreads();

    // ------- per-warp, barrier-free from here on -------
    const int lane = tid & 31;
    const int warp = tid >> 5;
    const int ts   = tid;                  // local row; warp owns [32w, 32w+32)

    // 3) HFD for this thread's timestep: all 10 k's.
    float c = 0.f, sx = 0.f, sy = 0.f, sxy = 0.f, sxx = 0.f;
    step_k<1>(s_d, ts, c, sx, sy, sxy, sxx);
    step_k<2>(s_d, ts, c, sx, sy, sxy, sxx);
    step_k<3>(s_d, ts, c, sx, sy, sxy, sxx);
    step_k<4>(s_d, ts, c, sx, sy, sxy, sxx);
    step_k<5>(s_d, ts, c, sx, sy, sxy, sxx);
    step_k<6>(s_d, ts, c, sx, sy, sxy, sxx);
    step_k<7>(s_d, ts, c, sx, sy, sxy, sxx);
    step_k<8>(s_d, ts, c, sx, sy, sxy, sxx);
    step_k<9>(s_d, ts, c, sx, sy, sxy, sxx);
    step_k<10>(s_d, ts, c, sx, sy, sxy, sxx);

    float hfd = 0.0f;
    {
        const float denom = c * sxx - sx * sx;
        if (c > 1.0f && denom != 0.0f)
            hfd = -(c * sxy - sx * sy) / denom;
    }

    // Block 0 warmup rows (t = ts < 49): growing-window generic path.
    if (blockIdx.x == 0 && ts <= BUF - 2) {
        hfd = 0.0f;
        if (ts >= MAX_K) {
            const int   nm1  = ts;
            const float nm1f = (float)nm1;
            const int   base = BUF - 1;       // s_p index of global price[0]
            float c2=0.f, sx2=0.f, sy2=0.f, sxy2=0.f, sxx2=0.f;
            for (int k = 1; k <= MAX_K; k++) {
                float acc = 0.0f;
                for (int m = 0; m < k; m++) {
                    const int len = (nm1 - m) / k + 1;
                    float s = 0.0f;
                    for (int q = m; q + k <= nm1; q += k)
                        s += fabsf(s_p[base + q + k] - s_p[base + q]);
                    if (len >= 2)
                        acc += s * nm1f / ((float)len * (float)k);
                }
                const float Lk = acc / (float)k;
                if (Lk > 0.0f) {
                    const float yk = __logf(Lk);
                    const float xk = __logf((float)k);
                    c2 += 1.f; sx2 += xk; sy2 += yk;
                    sxy2 += yk * xk; sxx2 += xk * xk;
                }
            }
            const float dn = c2 * sxx2 - sx2 * sx2;
            if (c2 > 1.0f && dn != 0.0f)
                hfd = -(c2 * sxy2 - sx2 * sy2) / dn;
        }
    }

    // 4) Warp streams its own 32x256 slice immediately (no block barrier).
    //    Lane l covers float4 columns l and l+32; row hfd via shfl broadcast.
    const float4 w4a = __ldg(((const float4*)w) + lane);
    const float4 w4b = __ldg(((const float4*)w) + lane + 32);
    const float4 b4a = __ldg(((const float4*)b) + lane);
    const float4 b4b = __ldg(((const float4*)b) + lane + 32);

    float4* const ob = out + ((size_t)t0 + (size_t)warp * 32) * (HIDDEN / 4) + lane;

    #pragma unroll
    for (int r = 0; r < 32; r++) {
        const float h = __shfl_sync(0xffffffffu, hfd, r);
        float4 o1, o2;
        o1.x = fmaxf(fmaf(h, w4a.x, b4a.x), 0.0f);
        o1.y = fmaxf(fmaf(h, w4a.y, b4a.y), 0.0f);
        o1.z = fmaxf(fmaf(h, w4a.z, b4a.z), 0.0f);
        o1.w = fmaxf(fmaf(h, w4a.w, b4a.w), 0.0f);
        o2.x = fmaxf(fmaf(h, w4b.x, b4b.x), 0.0f);
        o2.y = fmaxf(fmaf(h, w4b.y, b4b.y), 0.0f);
        o2.z = fmaxf(fmaf(h, w4b.z, b4b.z), 0.0f);
        o2.w = fmaxf(fmaf(h, w4b.w, b4b.w), 0.0f);
        __stcs(ob + (size_t)r * (HIDDEN / 4), o1);
        __stcs(ob + (size_t)r * (HIDDEN / 4) + 32, o2);
    }
}

// ---------------------------------------------------------------------------
extern "C" void kernel_launch(void* const* d_in, const int* in_sizes, int n_in,
                              void* d_out, int out_size)
{
    const float* x = (const float*)d_in[0];   // [T, 8]
    const float* w = (const float*)d_in[1];   // [256, 1] -> flat [256]
    const float* b = (const float*)d_in[2];   // [256]
    float4* out = (float4*)d_out;             // [T, 256] f32

    fused_hfd_kernel<<<T_STEPS / ROWS, BLK>>>(x, w, b, out);
}